// round 1
// baseline (speedup 1.0000x reference)
#include <cuda_runtime.h>

// Histogram matching: BINS=32, SIGMA=5, DELTA=1
// Shapes: dst, ref: (2,1,64,128,128) fp32; out same.
#define N_VOX   (64 * 128 * 128)   // 1048576 voxels per image
#define N_IMG   2
#define H_BLOCKS 37                // hist blocks per job (4 jobs * 37 = 148 = #SMs)
#define LUT_N   8192               // lerp intervals; nodes = LUT_N+1

// Scratch (device globals; fully rewritten every launch -> graph-replay safe)
__device__ float g_part[4 * H_BLOCKS * 32];     // per-block histogram partials
__device__ float g_lut[N_IMG * (LUT_N + 1)];    // matched-value LUT per image

// ---------------------------------------------------------------------------
// Kernel 1: soft histograms for 4 jobs (dst img0, dst img1, ref img0, ref img1)
// Telescoped sigmoids: bin c gets S(c)-S(c+1), S(c)=sigmoid(5*(x-c+0.5)).
// Only boundaries c in [j-3, j+4] (j=floor(x)) are non-saturated; chain the
// exp: one __expf, then multiply by e^-5 per step. 1 EX2 + 8 RCP per voxel.
// ---------------------------------------------------------------------------
__global__ void __launch_bounds__(256) hist_kernel(const float* __restrict__ dst,
                                                   const float* __restrict__ ref)
{
    __shared__ float hs[8 * 32 * 32];   // [warp][bin][lane], bank==lane: conflict-free
    __shared__ float part2[8 * 32];

    const int tid  = threadIdx.x;
    const int lane = tid & 31;
    const int warp = tid >> 5;
    const int job  = blockIdx.y;        // 0,1 = dst; 2,3 = ref
    const float* src = (job < 2 ? dst : ref) + (size_t)(job & 1) * N_VOX;

    for (int i = tid; i < 8 * 32 * 32; i += 256) hs[i] = 0.0f;
    __syncthreads();

    float* hp = &hs[warp * 32 * 32 + lane];   // index with + c*32

    const float4* src4 = (const float4*)src;
    const int nthreads = H_BLOCKS * 256;
    for (int i = blockIdx.x * 256 + tid; i < N_VOX / 4; i += nthreads) {
        float4 v = src4[i];
        float vals[4] = {v.x, v.y, v.z, v.w};
        #pragma unroll
        for (int e = 0; e < 4; e++) {
            float x = vals[e] * 31.0f;            // in [0, 31)
            int   j = (int)x;                     // floor
            // E = exp(-arg) at boundary c=j+4, arg=5*(x-j-3.5) in [-17.5,-12.5]
            float E  = __expf(5.0f * ((float)j + 3.5f - x));
            float Sp = 0.0f;                      // S(c+1), S(j+5)~=0
            #pragma unroll
            for (int b = 0; b < 8; b++) {
                int   c = j + 4 - b;
                float S = __fdividef(1.0f, 1.0f + E);
                if (c >= 0 && c <= 31) hp[c * 32] += (S - Sp);
                Sp = S;
                E *= 0.0067379469990854670966f;   // e^-5
            }
            int c = j - 4;                        // S(j-4) ~= 1
            if (c >= 0) hp[c * 32] += (1.0f - Sp);
        }
    }
    __syncthreads();

    // Reduce 8x32 lane-columns per bin. Skewed lane start -> conflict-free.
    {
        int w = warp, bin = lane;                 // 256 threads = 8 warps x 32 bins
        float s = 0.0f;
        #pragma unroll
        for (int i = 0; i < 32; i++) {
            int l = (lane + i) & 31;
            s += hs[(w * 32 + bin) * 32 + l];
        }
        part2[w * 32 + bin] = s;
    }
    __syncthreads();
    if (tid < 32) {
        float s = 0.0f;
        #pragma unroll
        for (int w = 0; w < 8; w++) s += part2[w * 32 + tid];
        g_part[(job * H_BLOCKS + blockIdx.x) * 32 + tid] = s;
    }
}

// ---------------------------------------------------------------------------
// Kernel 2: every block redundantly computes cdf + argmin tables (cheap),
// then blocks cooperatively build the matched-value LUT:
//   f(x) = (sum_k exp(-(x-k)^2/50) * table[k]) / (sum_k exp(...)) / 31
// ---------------------------------------------------------------------------
__global__ void __launch_bounds__(256) lut_kernel()
{
    __shared__ float cdf[4][32];
    __shared__ float tab[2][32];
    const int tid = threadIdx.x;

    if (tid < 128) {
        int job = tid >> 5, bin = tid & 31;
        float s = 0.0f;
        #pragma unroll 1
        for (int b = 0; b < H_BLOCKS; b++)
            s += g_part[(job * H_BLOCKS + b) * 32 + bin];
        cdf[job][bin] = s;                         // raw hist for now
    }
    __syncthreads();
    if (tid < 4) {                                 // normalize + cumsum (serial, tiny)
        float tot = 0.0f;
        for (int b = 0; b < 32; b++) tot += fabsf(cdf[tid][b]);
        tot = fmaxf(tot, 1e-12f);
        float run = 0.0f;
        for (int b = 0; b < 32; b++) { run += cdf[tid][b] / tot; cdf[tid][b] = run; }
    }
    __syncthreads();
    if (tid < 64) {                                // argmin tables (first-match ties)
        int bc = tid >> 5, i = tid & 31;
        float cd = cdf[bc][i];
        int best = 0;
        float bd = fabsf(cd - cdf[bc + 2][0]);
        for (int jj = 1; jj < 32; jj++) {
            float d = fabsf(cd - cdf[bc + 2][jj]);
            if (d < bd) { bd = d; best = jj; }
        }
        tab[bc][i] = (float)best;
    }
    __syncthreads();

    const int total = N_IMG * (LUT_N + 1);
    for (int e = blockIdx.x * blockDim.x + tid; e < total; e += gridDim.x * blockDim.x) {
        int im = e / (LUT_N + 1);
        int i  = e - im * (LUT_N + 1);
        float x = (float)i * (31.0f / (float)LUT_N);
        float num = 0.0f, den = 0.0f;
        #pragma unroll
        for (int k = 0; k < 32; k++) {
            float d = x - (float)k;
            float w = __expf(d * d * -0.02f);      // exp(-(x-k)^2/50)
            den += w;
            num += w * tab[im][k];
        }
        g_lut[e] = __fdividef(num, den) * (1.0f / 31.0f);
    }
}

// ---------------------------------------------------------------------------
// Kernel 3: per-voxel LUT lerp. lut coordinate u = v*8192 (v in [0,1)).
// ---------------------------------------------------------------------------
__global__ void __launch_bounds__(256) apply_kernel(const float* __restrict__ dst,
                                                    float* __restrict__ out)
{
    __shared__ float lut[LUT_N + 1];
    const int im  = blockIdx.y;
    const int tid = threadIdx.x;

    for (int i = tid; i < LUT_N + 1; i += 256)
        lut[i] = g_lut[im * (LUT_N + 1) + i];
    __syncthreads();

    const float4* in4  = (const float4*)(dst + (size_t)im * N_VOX);
    float4*       out4 = (float4*)(out + (size_t)im * N_VOX);
    const int nthreads = gridDim.x * 256;

    for (int i = blockIdx.x * 256 + tid; i < N_VOX / 4; i += nthreads) {
        float4 v = in4[i];
        float vals[4] = {v.x, v.y, v.z, v.w};
        float res[4];
        #pragma unroll
        for (int e = 0; e < 4; e++) {
            float u = vals[e] * (float)LUT_N;
            int idx = (int)u;
            idx = min(max(idx, 0), LUT_N - 1);
            float f = u - (float)idx;
            float a = lut[idx];
            float b = lut[idx + 1];
            res[e] = a + f * (b - a);
        }
        out4[i] = make_float4(res[0], res[1], res[2], res[3]);
    }
}

extern "C" void kernel_launch(void* const* d_in, const int* in_sizes, int n_in,
                              void* d_out, int out_size)
{
    const float* dst = (const float*)d_in[0];
    const float* ref = (const float*)d_in[1];
    float* out = (float*)d_out;

    hist_kernel<<<dim3(H_BLOCKS, 4), 256>>>(dst, ref);
    lut_kernel<<<64, 256>>>();
    apply_kernel<<<dim3(64, N_IMG), 256>>>(dst, out);
}